// round 4
// baseline (speedup 1.0000x reference)
#include <cuda_runtime.h>
#include <cuda_bf16.h>
#include <math.h>
#include <float.h>

// Problem constants (fixed by the dataset)
#define BQ 64          // batch (queries)
#define DIM 768        // hidden dim
#define NKEYS 262144   // datastore size
#define VOCAB 50257
#define KNN 8
#define INV_TEMP 0.1f  // 1/10
#define LAM 0.25f
#define EPSV 1e-10f

// 64 MiB scratch for scores [BQ][NKEYS]
__device__ float g_scores[(size_t)BQ * NKEYS];
__device__ float g_w[BQ * KNN];
__device__ int   g_tok[BQ * KNN];

// ---------------------------------------------------------------------------
// Kernel A: score GEMM.  s[b,n] = 2 * dot(q_b, k_n) - ||k_n||^2
// BM=64 (all queries), BN=64, BK=16. 256 threads, 4x4 micro-tile per thread.
// Keys are read from HBM exactly once (one block per key tile covers all B).
// ---------------------------------------------------------------------------
#define BN 64
#define BK 16

__global__ __launch_bounds__(256) void gemm_score_kernel(
    const float* __restrict__ Q,      // [BQ, DIM]
    const float* __restrict__ Keys)   // [NKEYS, DIM]
{
    __shared__ float As[BK][BQ];   // As[k][m]
    __shared__ float Bs[BK][BN];   // Bs[k][n]
    __shared__ float k2p[256];
    __shared__ float k2s[BN];

    const int tid = threadIdx.x;
    const int n0  = blockIdx.x * BN;

    // loader mapping: each thread loads one float4 per tile
    const int lr = tid >> 2;          // row 0..63 (m for A, local n for B)
    const int ls = (tid & 3) * 4;     // k-segment 0,4,8,12

    // compute mapping: 16x16 thread grid, 4x4 accumulators
    const int ty = tid >> 4;          // 0..15
    const int tx = tid & 15;          // 0..15

    float acc[4][4];
#pragma unroll
    for (int i = 0; i < 4; i++)
#pragma unroll
        for (int j = 0; j < 4; j++) acc[i][j] = 0.f;

    float k2part = 0.f;

    const float* qbase = Q + lr * DIM + ls;
    const float* kbase = Keys + (size_t)(n0 + lr) * DIM + ls;

    for (int kk = 0; kk < DIM; kk += BK) {
        float4 a4 = *(const float4*)(qbase + kk);
        float4 b4 = *(const float4*)(kbase + kk);
        As[ls + 0][lr] = a4.x; As[ls + 1][lr] = a4.y;
        As[ls + 2][lr] = a4.z; As[ls + 3][lr] = a4.w;
        Bs[ls + 0][lr] = b4.x; Bs[ls + 1][lr] = b4.y;
        Bs[ls + 2][lr] = b4.z; Bs[ls + 3][lr] = b4.w;
        k2part += b4.x * b4.x + b4.y * b4.y + b4.z * b4.z + b4.w * b4.w;
        __syncthreads();

#pragma unroll
        for (int k = 0; k < BK; k++) {
            float4 av = *(const float4*)(&As[k][ty * 4]);
            float4 bv = *(const float4*)(&Bs[k][tx * 4]);
            float a[4] = {av.x, av.y, av.z, av.w};
            float b[4] = {bv.x, bv.y, bv.z, bv.w};
#pragma unroll
            for (int i = 0; i < 4; i++)
#pragma unroll
                for (int j = 0; j < 4; j++)
                    acc[i][j] = fmaf(a[i], b[j], acc[i][j]);
        }
        __syncthreads();
    }

    // reduce ||k||^2 per local column n (4 loader threads per n)
    k2p[tid] = k2part;
    __syncthreads();
    if (tid < BN)
        k2s[tid] = k2p[tid * 4] + k2p[tid * 4 + 1] + k2p[tid * 4 + 2] + k2p[tid * 4 + 3];
    __syncthreads();

    // write scores: s = 2*dot - k2
#pragma unroll
    for (int i = 0; i < 4; i++) {
        int m = ty * 4 + i;
        float4 o;
        o.x = 2.f * acc[i][0] - k2s[tx * 4 + 0];
        o.y = 2.f * acc[i][1] - k2s[tx * 4 + 1];
        o.z = 2.f * acc[i][2] - k2s[tx * 4 + 2];
        o.w = 2.f * acc[i][3] - k2s[tx * 4 + 3];
        *(float4*)(g_scores + (size_t)m * NKEYS + n0 + tx * 4) = o;
    }
}

// ---------------------------------------------------------------------------
// Kernel B: per-row top-8 over NKEYS scores + softmax weights + token gather.
// One block per row, 256 threads. Thread-local top-8, then 8 block argmaxes.
// ---------------------------------------------------------------------------
__global__ __launch_bounds__(256) void topk_kernel(const int* __restrict__ values)
{
    const int row = blockIdx.x;
    const int tid = threadIdx.x;

    float tv[KNN];
    int   ti[KNN];
#pragma unroll
    for (int j = 0; j < KNN; j++) { tv[j] = -FLT_MAX; ti[j] = -1; }

    const float4* sp = (const float4*)(g_scores + (size_t)row * NKEYS);
    const int nvec = NKEYS / 4;   // 65536
    for (int i = tid; i < nvec; i += 256) {
        float4 s4 = sp[i];
        float v[4] = {s4.x, s4.y, s4.z, s4.w};
#pragma unroll
        for (int l = 0; l < 4; l++) {
            if (v[l] > tv[0]) {
                tv[0] = v[l]; ti[0] = i * 4 + l;
                // keep ascending order (tv[0] = current min of the 8)
#pragma unroll
                for (int j = 0; j < KNN - 1; j++) {
                    if (tv[j] > tv[j + 1]) {
                        float tmpv = tv[j]; tv[j] = tv[j + 1]; tv[j + 1] = tmpv;
                        int tmpi = ti[j]; ti[j] = ti[j + 1]; ti[j + 1] = tmpi;
                    }
                }
            }
        }
    }

    __shared__ float sv[256 * KNN];
    __shared__ int   si[256 * KNN];
#pragma unroll
    for (int j = 0; j < KNN; j++) { sv[tid * KNN + j] = tv[j]; si[tid * KNN + j] = ti[j]; }

    __shared__ float rv[256];
    __shared__ int   rp[256];
    __shared__ float topv[KNN];
    __shared__ int   topi[KNN];
    __syncthreads();

    for (int sel = 0; sel < KNN; sel++) {
        float bv = -FLT_MAX; int bp = -1;
#pragma unroll
        for (int j = 0; j < KNN; j++) {
            float v = sv[tid * KNN + j];
            if (v > bv) { bv = v; bp = tid * KNN + j; }
        }
        rv[tid] = bv; rp[tid] = bp;
        __syncthreads();
        for (int s = 128; s > 0; s >>= 1) {
            if (tid < s && rv[tid + s] > rv[tid]) { rv[tid] = rv[tid + s]; rp[tid] = rp[tid + s]; }
            __syncthreads();
        }
        if (tid == 0) {
            int p = rp[0];
            topv[sel] = sv[p];
            topi[sel] = si[p];
            sv[p] = -FLT_MAX;
        }
        __syncthreads();
    }

    if (tid == 0) {
        // weights = softmax(s_j / T), topv already sorted descending
        float m = topv[0];
        float e[KNN], sum = 0.f;
#pragma unroll
        for (int j = 0; j < KNN; j++) { e[j] = expf((topv[j] - m) * INV_TEMP); sum += e[j]; }
        float inv = 1.f / sum;
#pragma unroll
        for (int j = 0; j < KNN; j++) {
            g_w[row * KNN + j] = e[j] * inv;
            g_tok[row * KNN + j] = values[topi[j]];
        }
    }
}

// ---------------------------------------------------------------------------
// Kernel C: epilogue. Per row: softmax(base_logits), knn mix, 3 outputs.
// out layout: [interpolated | base | knn], each [BQ, VOCAB].
// ---------------------------------------------------------------------------
__global__ __launch_bounds__(512) void epilogue_kernel(
    const float* __restrict__ base, float* __restrict__ out)
{
    const int row = blockIdx.x;
    const int tid = threadIdx.x;
    const float* br = base + (size_t)row * VOCAB;

    __shared__ float red[512];

    // pass 1: max
    float m = -FLT_MAX;
    for (int i = tid; i < VOCAB; i += 512) m = fmaxf(m, br[i]);
    red[tid] = m; __syncthreads();
    for (int s = 256; s > 0; s >>= 1) {
        if (tid < s) red[tid] = fmaxf(red[tid], red[tid + s]);
        __syncthreads();
    }
    const float mx = red[0];
    __syncthreads();

    // pass 2: sum(exp)
    float sacc = 0.f;
    for (int i = tid; i < VOCAB; i += 512) sacc += expf(br[i] - mx);
    red[tid] = sacc; __syncthreads();
    for (int s = 256; s > 0; s >>= 1) {
        if (tid < s) red[tid] += red[tid + s];
        __syncthreads();
    }
    const float invZ = 1.f / red[0];

    float w[KNN]; int tk[KNN];
#pragma unroll
    for (int j = 0; j < KNN; j++) { w[j] = g_w[row * KNN + j]; tk[j] = g_tok[row * KNN + j]; }

    // softmax(knn_logits) = (tp + eps) / (sum(tp) + V*eps), sum(tp) = 1
    const float invden = 1.f / (1.f + (float)VOCAB * EPSV);

    float* oi = out + (size_t)row * VOCAB;
    float* ob = out + (size_t)BQ * VOCAB + (size_t)row * VOCAB;
    float* ok = out + (size_t)2 * BQ * VOCAB + (size_t)row * VOCAB;

    for (int i = tid; i < VOCAB; i += 512) {
        float b = br[i];
        float sb = expf(b - mx) * invZ;
        float tp = 0.f;
#pragma unroll
        for (int j = 0; j < KNN; j++) tp += (tk[j] == i) ? w[j] : 0.f;
        float kl = logf(tp + EPSV);
        float p = (1.f - LAM) * sb + LAM * (tp + EPSV) * invden;
        oi[i] = logf(p);
        ob[i] = b;
        ok[i] = kl;
    }
}

// ---------------------------------------------------------------------------
extern "C" void kernel_launch(void* const* d_in, const int* in_sizes, int n_in,
                              void* d_out, int out_size)
{
    const float* Q    = (const float*)d_in[0];       // [64, 768]
    const float* BL   = (const float*)d_in[1];       // [64, 50257]
    const float* Keys = (const float*)d_in[2];       // [262144, 768]
    const int*   Vals = (const int*)d_in[3];         // [262144] (int32: JAX x64 disabled)
    float* out = (float*)d_out;

    gemm_score_kernel<<<NKEYS / BN, 256>>>(Q, Keys);
    topk_kernel<<<BQ, 256>>>(Vals);
    epilogue_kernel<<<BQ, 512>>>(BL, out);
}

// round 5
// speedup vs baseline: 1.2059x; 1.2059x over previous
#include <cuda_runtime.h>
#include <cuda_bf16.h>
#include <math.h>
#include <float.h>

#define BQ 64
#define DIM 768
#define NKEYS 262144
#define VOCAB 50257
#define KNN 8
#define INV_TEMP 0.1f
#define LAM 0.25f
#define EPSV 1e-10f

// scratch
__device__ float g_scores[(size_t)BQ * NKEYS];          // 64 MiB
__device__ float g_w[BQ * KNN];
__device__ int   g_tok[BQ * KNN];
#define TCH 16                                           // topk chunks per row
__device__ float g_cand_v[BQ * TCH * KNN];
__device__ int   g_cand_i[BQ * TCH * KNN];
#define ECH 8                                            // epilogue chunks per row
__device__ float2 g_ms[BQ * ECH];                        // per-chunk (max, sumexp)

// ---------------------------------------------------------------------------
// Kernel A: score GEMM. s[b,n] = 2*q.k - ||k||^2
// BM=64, BN=256, BK=16, 256 threads, 8x8 micro-tile. 1 B LDS per FMA.
// ---------------------------------------------------------------------------
#define BN 256
#define BK 16

__global__ __launch_bounds__(256, 2) void gemm_score_kernel(
    const float* __restrict__ Q, const float* __restrict__ Keys)
{
    __shared__ float As[BK][BQ];    // [k][m]
    __shared__ float Bs[BK][BN];    // [k][n]
    __shared__ float k2sm[BN];

    const int tid = threadIdx.x;
    const int n0  = blockIdx.x * BN;

    // A loader: thread -> (row 0..63, k-seg 0..3)
    const int alr = tid >> 2;
    const int als = (tid & 3) * 4;
    // B loader: thread t loads full 16-float k-slice of key row n0+t
    const float* kb = Keys + (size_t)(n0 + tid) * DIM;
    const float* qb = Q + alr * DIM + als;

    // compute mapping: tn 0..31 (n), tm 0..7 (m), 8x8 accum
    const int tn = tid >> 3;
    const int tm = tid & 7;

    float acc[8][8];
#pragma unroll
    for (int i = 0; i < 8; i++)
#pragma unroll
        for (int j = 0; j < 8; j++) acc[i][j] = 0.f;

    float k2part = 0.f;

    for (int kk = 0; kk < DIM; kk += BK) {
        float4 a4 = *(const float4*)(qb + kk);
        float4 b0 = *(const float4*)(kb + kk);
        float4 b1 = *(const float4*)(kb + kk + 4);
        float4 b2 = *(const float4*)(kb + kk + 8);
        float4 b3 = *(const float4*)(kb + kk + 12);

        As[als + 0][alr] = a4.x; As[als + 1][alr] = a4.y;
        As[als + 2][alr] = a4.z; As[als + 3][alr] = a4.w;

        Bs[0][tid] = b0.x;  Bs[1][tid] = b0.y;  Bs[2][tid] = b0.z;  Bs[3][tid] = b0.w;
        Bs[4][tid] = b1.x;  Bs[5][tid] = b1.y;  Bs[6][tid] = b1.z;  Bs[7][tid] = b1.w;
        Bs[8][tid] = b2.x;  Bs[9][tid] = b2.y;  Bs[10][tid] = b2.z; Bs[11][tid] = b2.w;
        Bs[12][tid] = b3.x; Bs[13][tid] = b3.y; Bs[14][tid] = b3.z; Bs[15][tid] = b3.w;

        k2part += b0.x*b0.x + b0.y*b0.y + b0.z*b0.z + b0.w*b0.w
                + b1.x*b1.x + b1.y*b1.y + b1.z*b1.z + b1.w*b1.w
                + b2.x*b2.x + b2.y*b2.y + b2.z*b2.z + b2.w*b2.w
                + b3.x*b3.x + b3.y*b3.y + b3.z*b3.z + b3.w*b3.w;
        __syncthreads();

#pragma unroll
        for (int k = 0; k < BK; k++) {
            float4 av0 = *(const float4*)(&As[k][tm * 8]);
            float4 av1 = *(const float4*)(&As[k][tm * 8 + 4]);
            float4 bv0 = *(const float4*)(&Bs[k][tn * 8]);
            float4 bv1 = *(const float4*)(&Bs[k][tn * 8 + 4]);
            float a[8] = {av0.x, av0.y, av0.z, av0.w, av1.x, av1.y, av1.z, av1.w};
            float b[8] = {bv0.x, bv0.y, bv0.z, bv0.w, bv1.x, bv1.y, bv1.z, bv1.w};
#pragma unroll
            for (int i = 0; i < 8; i++)
#pragma unroll
                for (int j = 0; j < 8; j++)
                    acc[i][j] = fmaf(a[i], b[j], acc[i][j]);
        }
        __syncthreads();
    }

    k2sm[tid] = k2part;
    __syncthreads();

    float k2[8];
#pragma unroll
    for (int j = 0; j < 8; j++) k2[j] = k2sm[tn * 8 + j];

#pragma unroll
    for (int i = 0; i < 8; i++) {
        int m = tm * 8 + i;
        float* op = g_scores + (size_t)m * NKEYS + n0 + tn * 8;
        float4 o0, o1;
        o0.x = 2.f*acc[i][0] - k2[0]; o0.y = 2.f*acc[i][1] - k2[1];
        o0.z = 2.f*acc[i][2] - k2[2]; o0.w = 2.f*acc[i][3] - k2[3];
        o1.x = 2.f*acc[i][4] - k2[4]; o1.y = 2.f*acc[i][5] - k2[5];
        o1.z = 2.f*acc[i][6] - k2[6]; o1.w = 2.f*acc[i][7] - k2[7];
        *(float4*)(op)     = o0;
        *(float4*)(op + 4) = o1;
    }
}

// ---------------------------------------------------------------------------
// Kernel B1: per-(row,chunk) top-8.  grid (TCH, BQ), 256 threads.
// chunk = NKEYS/TCH = 16384 elements.
// ---------------------------------------------------------------------------
#define CHUNK_N (NKEYS / TCH)

__global__ __launch_bounds__(256) void topk_stage1(void)
{
    const int chunk = blockIdx.x;
    const int row   = blockIdx.y;
    const int tid   = threadIdx.x;

    float tv[KNN]; int ti[KNN];
#pragma unroll
    for (int j = 0; j < KNN; j++) { tv[j] = -FLT_MAX; ti[j] = -1; }

    const float4* sp = (const float4*)(g_scores + (size_t)row * NKEYS + (size_t)chunk * CHUNK_N);
    const int nvec = CHUNK_N / 4;   // 4096
    for (int i = tid; i < nvec; i += 256) {
        float4 s4 = sp[i];
        float v[4] = {s4.x, s4.y, s4.z, s4.w};
#pragma unroll
        for (int l = 0; l < 4; l++) {
            if (v[l] > tv[0]) {
                tv[0] = v[l]; ti[0] = chunk * CHUNK_N + i * 4 + l;
#pragma unroll
                for (int j = 0; j < KNN - 1; j++) {
                    if (tv[j] > tv[j + 1]) {
                        float t0 = tv[j]; tv[j] = tv[j+1]; tv[j+1] = t0;
                        int   t1 = ti[j]; ti[j] = ti[j+1]; ti[j+1] = t1;
                    }
                }
            }
        }
    }

    __shared__ float sv[256 * KNN];
    __shared__ int   si[256 * KNN];
#pragma unroll
    for (int j = 0; j < KNN; j++) { sv[tid*KNN+j] = tv[j]; si[tid*KNN+j] = ti[j]; }

    __shared__ float rv[256];
    __shared__ int   rp[256];
    __syncthreads();

    for (int sel = 0; sel < KNN; sel++) {
        float bv = -FLT_MAX; int bp = 0;
#pragma unroll
        for (int j = 0; j < KNN; j++) {
            float v = sv[tid*KNN+j];
            if (v > bv) { bv = v; bp = tid*KNN+j; }
        }
        rv[tid] = bv; rp[tid] = bp;
        __syncthreads();
        for (int s = 128; s > 0; s >>= 1) {
            if (tid < s && rv[tid+s] > rv[tid]) { rv[tid] = rv[tid+s]; rp[tid] = rp[tid+s]; }
            __syncthreads();
        }
        if (tid == 0) {
            int p = rp[0];
            g_cand_v[(row * TCH + chunk) * KNN + sel] = sv[p];
            g_cand_i[(row * TCH + chunk) * KNN + sel] = si[p];
            sv[p] = -FLT_MAX;
        }
        __syncthreads();
    }
}

// ---------------------------------------------------------------------------
// Kernel B2: merge TCH*KNN = 128 candidates per row -> top-8, weights, tokens.
// grid BQ, 128 threads.
// ---------------------------------------------------------------------------
__global__ __launch_bounds__(128) void topk_stage2(const int* __restrict__ values)
{
    const int row = blockIdx.x;
    const int tid = threadIdx.x;

    __shared__ float sv[128];
    __shared__ int   si[128];
    __shared__ float rv[128];
    __shared__ int   rp[128];
    __shared__ float topv[KNN];
    __shared__ int   topi[KNN];

    sv[tid] = g_cand_v[row * 128 + tid];
    si[tid] = g_cand_i[row * 128 + tid];
    __syncthreads();

    for (int sel = 0; sel < KNN; sel++) {
        rv[tid] = sv[tid]; rp[tid] = tid;
        __syncthreads();
        for (int s = 64; s > 0; s >>= 1) {
            if (tid < s && rv[tid+s] > rv[tid]) { rv[tid] = rv[tid+s]; rp[tid] = rp[tid+s]; }
            __syncthreads();
        }
        if (tid == 0) {
            int p = rp[0];
            topv[sel] = sv[p];
            topi[sel] = si[p];
            sv[p] = -FLT_MAX;
        }
        __syncthreads();
    }

    if (tid == 0) {
        float m = topv[0];
        float e[KNN], sum = 0.f;
#pragma unroll
        for (int j = 0; j < KNN; j++) { e[j] = expf((topv[j] - m) * INV_TEMP); sum += e[j]; }
        float inv = 1.f / sum;
#pragma unroll
        for (int j = 0; j < KNN; j++) {
            g_w[row * KNN + j]   = e[j] * inv;
            g_tok[row * KNN + j] = values[topi[j]];
        }
    }
}

// ---------------------------------------------------------------------------
// Kernel E1: per-(row,chunk) softmax partials (max, sumexp). grid (ECH, BQ).
// ---------------------------------------------------------------------------
#define VCH ((VOCAB + ECH - 1) / ECH)   // 6283

__global__ __launch_bounds__(256) void epi_partials(const float* __restrict__ base)
{
    const int chunk = blockIdx.x;
    const int row   = blockIdx.y;
    const int tid   = threadIdx.x;
    const int start = chunk * VCH;
    const int end   = min(start + VCH, VOCAB);
    const float* br = base + (size_t)row * VOCAB;

    __shared__ float red[256];

    float m = -FLT_MAX;
    for (int i = start + tid; i < end; i += 256) m = fmaxf(m, br[i]);
    red[tid] = m; __syncthreads();
    for (int s = 128; s > 0; s >>= 1) {
        if (tid < s) red[tid] = fmaxf(red[tid], red[tid+s]);
        __syncthreads();
    }
    const float mx = red[0];
    __syncthreads();

    float sacc = 0.f;
    for (int i = start + tid; i < end; i += 256) sacc += expf(br[i] - mx);
    red[tid] = sacc; __syncthreads();
    for (int s = 128; s > 0; s >>= 1) {
        if (tid < s) red[tid] += red[tid+s];
        __syncthreads();
    }
    if (tid == 0) g_ms[row * ECH + chunk] = make_float2(mx, red[0]);
}

// ---------------------------------------------------------------------------
// Kernel E2: elementwise mix + 3 output streams. grid (ECH, BQ), 256 threads.
// ---------------------------------------------------------------------------
__global__ __launch_bounds__(256) void epi_write(
    const float* __restrict__ base, float* __restrict__ out)
{
    const int chunk = blockIdx.x;
    const int row   = blockIdx.y;
    const int tid   = threadIdx.x;
    const int start = chunk * VCH;
    const int end   = min(start + VCH, VOCAB);
    const float* br = base + (size_t)row * VOCAB;

    // combine the ECH partials (deterministic fixed order)
    float mx = -FLT_MAX;
#pragma unroll
    for (int c = 0; c < ECH; c++) mx = fmaxf(mx, g_ms[row * ECH + c].x);
    float Z = 0.f;
#pragma unroll
    for (int c = 0; c < ECH; c++) {
        float2 p = g_ms[row * ECH + c];
        Z += p.y * expf(p.x - mx);
    }
    const float invZ = 1.f / Z;

    float w[KNN]; int tk[KNN];
#pragma unroll
    for (int j = 0; j < KNN; j++) { w[j] = g_w[row*KNN+j]; tk[j] = g_tok[row*KNN+j]; }

    const float invden = 1.f / (1.f + (float)VOCAB * EPSV);

    float* oi = out + (size_t)row * VOCAB;
    float* ob = out + (size_t)BQ * VOCAB + (size_t)row * VOCAB;
    float* ok = out + (size_t)2 * BQ * VOCAB + (size_t)row * VOCAB;

    for (int i = start + tid; i < end; i += 256) {
        float b  = br[i];
        float sb = expf(b - mx) * invZ;
        float tp = 0.f;
#pragma unroll
        for (int j = 0; j < KNN; j++) tp += (tk[j] == i) ? w[j] : 0.f;
        float p = (1.f - LAM) * sb + LAM * (tp + EPSV) * invden;
        oi[i] = logf(p);
        ob[i] = b;
        ok[i] = logf(tp + EPSV);
    }
}

// ---------------------------------------------------------------------------
extern "C" void kernel_launch(void* const* d_in, const int* in_sizes, int n_in,
                              void* d_out, int out_size)
{
    const float* Q    = (const float*)d_in[0];
    const float* BL   = (const float*)d_in[1];
    const float* Keys = (const float*)d_in[2];
    const int*   Vals = (const int*)d_in[3];
    float* out = (float*)d_out;

    gemm_score_kernel<<<NKEYS / BN, 256>>>(Q, Keys);
    topk_stage1<<<dim3(TCH, BQ), 256>>>();
    topk_stage2<<<BQ, 128>>>(Vals);
    epi_partials<<<dim3(ECH, BQ), 256>>>(BL);
    epi_write<<<dim3(ECH, BQ), 256>>>(BL, out);
}